// round 10
// baseline (speedup 1.0000x reference)
#include <cuda_runtime.h>
#include <math.h>

#define NTAGS 32
#define SLEN 512
#define START_TAG 30
#define STOP_TAG 31
#define NB 8   // batches per warp (rows 0..7 of the m16 tile; rows 8..15 zero)

typedef unsigned int u32;

__device__ __forceinline__ u32 pack_bf2(float lo, float hi) {
    u32 d;
    asm("cvt.rn.bf16x2.f32 %0, %1, %2;" : "=r"(d) : "f"(hi), "f"(lo));
    return d;
}

// D = A @ B (m16n8k16 bf16, fp32 accum from zero). Only rows 0..7 used:
// a1/a3 (rows 8..15) are zero; we consume d0,d1 (row = lane>>2).
__device__ __forceinline__ void mma8(float &d0, float &d1,
                                     u32 a0, u32 a2, u32 b0, u32 b1) {
    float d2, d3;
    asm("mma.sync.aligned.m16n8k16.row.col.f32.bf16.bf16.f32 "
        "{%0,%1,%2,%3}, {%4,%5,%6,%7}, {%8,%9}, {%10,%11,%12,%13};"
        : "=f"(d0), "=f"(d1), "=f"(d2), "=f"(d3)
        : "r"(a0), "r"(0u), "r"(a2), "r"(0u), "r"(b0), "r"(b1),
          "f"(0.f), "f"(0.f), "f"(0.f), "f"(0.f));
}

// One 4-step block: pe = exp(raw) (+ pending renorm folded into step 0),
// refill raw with block t0+8, run 4 MMA recurrence steps, compute new
// pending renorm exponent at the last step.
__device__ __forceinline__ void process_block(
    float2 (&raw)[4][4], const float* pb, int t0,
    u32 (&Aa)[2][2], const u32 (&Bf)[2][4][2],
    int &esum, int &pend, float (&v)[4][2], int lane)
{
    // exp of this block's emissions (loaded two blocks ago) — off-chain
    float pe[4][4][2];
#pragma unroll
    for (int u = 0; u < 4; u++)
#pragma unroll
        for (int n = 0; n < 4; n++) {
            pe[u][n][0] = __expf(raw[u][n].x);
            pe[u][n][1] = __expf(raw[u][n].y);
        }
    // refill this buffer with block t0+8 (clamped; tail refills unused)
    const int nbk = (t0 + 8 < SLEN) ? (t0 + 8) : (SLEN - 4);
#pragma unroll
    for (int u = 0; u < 4; u++)
#pragma unroll
        for (int n = 0; n < 4; n++)
            raw[u][n] = *(const float2*)(pb + (size_t)(nbk + u) * NTAGS + n * 8);

    // apply pending power-of-2 renorm by folding exact 2^-pend into step-0 pe
    esum += pend;
    const float sc = __int_as_float((127 - pend) << 23);
#pragma unroll
    for (int n = 0; n < 4; n++) { pe[0][n][0] *= sc; pe[0][n][1] *= sc; }
    pend = 0;

#pragma unroll
    for (int u = 0; u < 4; u++) {
        u32 newA[4];
#pragma unroll
        for (int n = 0; n < 4; n++) {
            float d0a, d1a, d0b, d1b;
            mma8(d0a, d1a, Aa[0][0], Aa[0][1], Bf[0][n][0], Bf[0][n][1]);
            mma8(d0b, d1b, Aa[1][0], Aa[1][1], Bf[1][n][0], Bf[1][n][1]);
            v[n][0] = (d0a + d0b) * pe[u][n][0];
            v[n][1] = (d1a + d1b) * pe[u][n][1];
            newA[n] = pack_bf2(v[n][0], v[n][1]);
        }
        // accumulator(m16n8) -> next A fragment(m16k16): tile n feeds
        // k-cols [8n, 8n+8) — the classic P-reuse identity, no shuffles.
        Aa[0][0] = newA[0]; Aa[0][1] = newA[1];
        Aa[1][0] = newA[2]; Aa[1][1] = newA[3];
        if (u == 3) {
            // row max over this lane's 8 products, then across the quad
            float m = fmaxf(fmaxf(fmaxf(v[0][0], v[0][1]),
                                  fmaxf(v[1][0], v[1][1])),
                            fmaxf(fmaxf(v[2][0], v[2][1]),
                                  fmaxf(v[3][0], v[3][1])));
            m = fmaxf(m, __shfl_xor_sync(0xffffffffu, m, 1));
            m = fmaxf(m, __shfl_xor_sync(0xffffffffu, m, 2));
            const int e = (__float_as_int(m) >> 23) - 127;
            pend = min(max(e, -126), 126);
        }
    }
}

// One warp (= one 32-thread CTA) advances 8 independent CRF chains with the
// tensor core: W'[8x32] = W @ E as m16n8k16 bf16 MMAs (4 n-tiles x 2 k-chunks,
// parallel-k). W lives entirely in A-fragment registers; E in B-fragment
// registers; NO shared memory in the recurrence (the smem crossbar was the
// measured binder of all previous rounds). Emissions are LDG.64'd directly
// into fragment positions (each quad covers a full 128B row), 2 blocks deep.
// Exp-domain + deferred exact power-of-2 renorm as validated in rounds 6-8.
__global__ __launch_bounds__(32)
void crf_fwd_kernel(const float* __restrict__ feats,
                    const float* __restrict__ trans,
                    float* __restrict__ out) {
    const int lane = threadIdx.x;
    const int g = lane >> 2;    // batch row 0..7
    const int tid = lane & 3;
    const int base = blockIdx.x * NB;

    // B fragments of E (E[j,i] = exp(trans[i,j])): Bf[kc][n][r]
    // b0 holds (k=tid*2, n=g),(k=tid*2+1, n=g); b1 same with k+8.
    u32 Bf[2][4][2];
#pragma unroll
    for (int kc = 0; kc < 2; kc++)
#pragma unroll
        for (int n = 0; n < 4; n++) {
            const int i = n * 8 + g;
            const int j0 = kc * 16 + tid * 2;
            float e0 = __expf(trans[i * NTAGS + j0]);
            float e1 = __expf(trans[i * NTAGS + j0 + 1]);
            float e2 = __expf(trans[i * NTAGS + j0 + 8]);
            float e3 = __expf(trans[i * NTAGS + j0 + 9]);
            Bf[kc][n][0] = pack_bf2(e0, e1);
            Bf[kc][n][1] = pack_bf2(e2, e3);
        }
    // stop-transition weights for this lane's 8 tag slots
    float eS[4][2];
#pragma unroll
    for (int n = 0; n < 4; n++) {
        eS[n][0] = __expf(trans[STOP_TAG * NTAGS + n * 8 + tid * 2]);
        eS[n][1] = __expf(trans[STOP_TAG * NTAGS + n * 8 + tid * 2 + 1]);
    }

    // emission base: row (base+g), tag column tid*2 (8B-aligned float2 loads)
    const float* pb = feats + (size_t)(base + g) * SLEN * NTAGS + tid * 2;

    // A fragments (bf16x2): Aa[kc][0] = cols kc*16+tid*2, Aa[kc][1] = +8.
    // init: w one-hot at tag 30 -> chunk 1, a2 slot, tid==3, lo half.
    u32 Aa[2][2] = {{0u, 0u}, {0u, (tid == 3) ? 0x00003F80u : 0u}};

    // two 4-step blocks of raw emissions in flight
    float2 rawA[4][4], rawB[4][4];
#pragma unroll
    for (int u = 0; u < 4; u++)
#pragma unroll
        for (int n = 0; n < 4; n++) {
            rawA[u][n] = *(const float2*)(pb + (size_t)u * NTAGS + n * 8);
            rawB[u][n] = *(const float2*)(pb + (size_t)(4 + u) * NTAGS + n * 8);
        }

    int esum = 0, pend = 0;
    float v[4][2];

    for (int tb = 0; tb < SLEN; tb += 8) {
        process_block(rawA, pb, tb,     Aa, Bf, esum, pend, v, lane);
        process_block(rawB, pb, tb + 4, Aa, Bf, esum, pend, v, lane);
    }

    // terminate: logZ_b = esum*ln2 + log( sum_i w[b,i] * exp(T[STOP,i]) )
    // (final block's pending exponent was never applied to w -> excluded)
    float s = 0.f;
#pragma unroll
    for (int n = 0; n < 4; n++)
        s += v[n][0] * eS[n][0] + v[n][1] * eS[n][1];
    s += __shfl_xor_sync(0xffffffffu, s, 1);
    s += __shfl_xor_sync(0xffffffffu, s, 2);
    if (tid == 0)
        out[base + g] =
            (float)((double)esum * 0.6931471805599453 + log((double)s));
}

extern "C" void kernel_launch(void* const* d_in, const int* in_sizes, int n_in,
                              void* d_out, int out_size) {
    const float* feats = (const float*)d_in[0];
    const float* trans = (const float*)d_in[1];
    float* out = (float*)d_out;
    const int B = in_sizes[0] / (SLEN * NTAGS);
    crf_fwd_kernel<<<B / NB, 32>>>(feats, trans, out);  // 8 batches per warp
}

// round 15
// speedup vs baseline: 1.6570x; 1.6570x over previous
#include <cuda_runtime.h>
#include <math.h>

#define NTAGS 32
#define SLEN 512
#define HALF 256
#define START_TAG 30
#define STOP_TAG 31
#define NB 8   // batches per warp pair (rows 0..7 of m16; rows 8..15 zero)

typedef unsigned int u32;

__device__ __forceinline__ u32 pack_bf2(float lo, float hi) {
    u32 d;
    asm("cvt.rn.bf16x2.f32 %0, %1, %2;" : "=r"(d) : "f"(hi), "f"(lo));
    return d;
}

// D = A @ B (m16n8k16 bf16, fp32 accum from zero). Rows 8..15 zero.
__device__ __forceinline__ void mma8(float &d0, float &d1,
                                     u32 a0, u32 a2, u32 b0, u32 b1) {
    float d2, d3;
    asm("mma.sync.aligned.m16n8k16.row.col.f32.bf16.bf16.f32 "
        "{%0,%1,%2,%3}, {%4,%5,%6,%7}, {%8,%9}, {%10,%11,%12,%13};"
        : "=f"(d0), "=f"(d1), "=f"(d2), "=f"(d3)
        : "r"(a0), "r"(0u), "r"(a2), "r"(0u), "r"(b0), "r"(b1),
          "f"(0.f), "f"(0.f), "f"(0.f), "f"(0.f));
}

// quad max -> per-batch pending power-of-2 exponent
__device__ __forceinline__ int quad_exp(const float (&v)[4][2]) {
    float m = fmaxf(fmaxf(fmaxf(v[0][0], v[0][1]), fmaxf(v[1][0], v[1][1])),
                    fmaxf(fmaxf(v[2][0], v[2][1]), fmaxf(v[3][0], v[3][1])));
    m = fmaxf(m, __shfl_xor_sync(0xffffffffu, m, 1));
    m = fmaxf(m, __shfl_xor_sync(0xffffffffu, m, 2));
    return min(max((__float_as_int(m) >> 23) - 127, -126), 126);
}

// FORWARD block (4 steps): v' = (v @ E) * pe, pe applied AFTER the matvec.
__device__ __forceinline__ void fwd_block(
    float2 (&raw)[4][4], const float* pb, int t0,
    u32 (&Aa)[2][2], const u32 (&Bf)[2][4][2],
    int &esum, int &pend, float (&v)[4][2])
{
    float pe[4][4][2];
#pragma unroll
    for (int u = 0; u < 4; u++)
#pragma unroll
        for (int n = 0; n < 4; n++) {
            pe[u][n][0] = __expf(raw[u][n].x);
            pe[u][n][1] = __expf(raw[u][n].y);
        }
    const int nbk = (t0 + 8 < HALF) ? (t0 + 8) : (HALF - 4);
#pragma unroll
    for (int u = 0; u < 4; u++)
#pragma unroll
        for (int n = 0; n < 4; n++)
            raw[u][n] = *(const float2*)(pb + (size_t)(nbk + u) * NTAGS + n * 8);

    esum += pend;
    const float sc = __int_as_float((127 - pend) << 23);
#pragma unroll
    for (int n = 0; n < 4; n++) { pe[0][n][0] *= sc; pe[0][n][1] *= sc; }
    pend = 0;

#pragma unroll
    for (int u = 0; u < 4; u++) {
        u32 newA[4];
#pragma unroll
        for (int n = 0; n < 4; n++) {
            float d0a, d1a, d0b, d1b;
            mma8(d0a, d1a, Aa[0][0], Aa[0][1], Bf[0][n][0], Bf[0][n][1]);
            mma8(d0b, d1b, Aa[1][0], Aa[1][1], Bf[1][n][0], Bf[1][n][1]);
            v[n][0] = (d0a + d0b) * pe[u][n][0];
            v[n][1] = (d1a + d1b) * pe[u][n][1];
            newA[n] = pack_bf2(v[n][0], v[n][1]);
        }
        Aa[0][0] = newA[0]; Aa[0][1] = newA[1];
        Aa[1][0] = newA[2]; Aa[1][1] = newA[3];
        if (u == 3) pend = quad_exp(v);
    }
}

// BACKWARD block (4 steps): v' = (v .* pe) @ E^T, pe applied BEFORE the matvec.
// Block bb covers steps 511-(4bb) .. 508-(4bb); raw[u] holds row 511-(4bb+u).
__device__ __forceinline__ void bwd_block(
    float2 (&raw)[4][4], const float* pb, int bb,
    u32 (&Aa)[2][2], const u32 (&Bf)[2][4][2],
    int &esum, int &pend, float (&v)[4][2])
{
    float pe[4][4][2];
#pragma unroll
    for (int u = 0; u < 4; u++)
#pragma unroll
        for (int n = 0; n < 4; n++) {
            pe[u][n][0] = __expf(raw[u][n].x);
            pe[u][n][1] = __expf(raw[u][n].y);
        }
    const int bbc = (bb + 2 < HALF / 4) ? (bb + 2) : (HALF / 4 - 1);
#pragma unroll
    for (int u = 0; u < 4; u++)
#pragma unroll
        for (int n = 0; n < 4; n++)
            raw[u][n] = *(const float2*)(
                pb + (size_t)(SLEN - 1 - (bbc * 4 + u)) * NTAGS + n * 8);

    esum += pend;
    const float sc = __int_as_float((127 - pend) << 23);
#pragma unroll
    for (int n = 0; n < 4; n++) { pe[0][n][0] *= sc; pe[0][n][1] *= sc; }
    pend = 0;

#pragma unroll
    for (int u = 0; u < 4; u++) {
        // A = pack(v .* pe)  (emission absorbed before the transposed matvec)
        Aa[0][0] = pack_bf2(v[0][0] * pe[u][0][0], v[0][1] * pe[u][0][1]);
        Aa[0][1] = pack_bf2(v[1][0] * pe[u][1][0], v[1][1] * pe[u][1][1]);
        Aa[1][0] = pack_bf2(v[2][0] * pe[u][2][0], v[2][1] * pe[u][2][1]);
        Aa[1][1] = pack_bf2(v[3][0] * pe[u][3][0], v[3][1] * pe[u][3][1]);
#pragma unroll
        for (int n = 0; n < 4; n++) {
            float d0a, d1a, d0b, d1b;
            mma8(d0a, d1a, Aa[0][0], Aa[0][1], Bf[0][n][0], Bf[0][n][1]);
            mma8(d0b, d1b, Aa[1][0], Aa[1][1], Bf[1][n][0], Bf[1][n][1]);
            v[n][0] = d0a + d0b;
            v[n][1] = d1a + d1b;
        }
        if (u == 3) pend = quad_exp(v);
    }
}

// CTA = 64 threads = 2 warps on the same 8 batches.
// Warp 0: forward alpha over steps 0..255.  Warp 1: backward beta from the
// STOP vector over steps 511..256 (beta_t = M_t^T beta_{t+1}).  Exact split:
// logZ_b = log( sum_j alpha[b,j] * beta[b,j] ) + (esum_f+esum_b)*ln2.
// Halves the sequential depth (the measured binder at occ=2.6%) and doubles
// warps 256 -> 512. W/beta live in A-fragment registers; E / E^T in
// B-fragments; no smem in the recurrence. Per-batch (quad-uniform) deferred
// power-of-2 renorm as validated in round 10.
__global__ __launch_bounds__(64)
void crf_fwd_kernel(const float* __restrict__ feats,
                    const float* __restrict__ trans,
                    float* __restrict__ out) {
    __shared__ float sbeta[NB][NTAGS];
    __shared__ int sesum[NB];
    const int lane = threadIdx.x & 31;
    const int wid = threadIdx.x >> 5;
    const int g = lane >> 2;      // batch row 0..7
    const int tid = lane & 3;
    const int base = blockIdx.x * NB;

    // emission base: row (base+g), tag column tid*2
    const float* pb = feats + (size_t)(base + g) * SLEN * NTAGS + tid * 2;

    int esum = 0, pend = 0;
    float v[4][2];
    u32 Bf[2][4][2];
    u32 Aa[2][2];
    float2 rawA[4][4], rawB[4][4];

    if (wid == 0) {
        // ---- FORWARD: B[k=j][n=i] = E[i,j] = exp(trans[i*NT+j]) ----
#pragma unroll
        for (int kc = 0; kc < 2; kc++)
#pragma unroll
            for (int n = 0; n < 4; n++) {
                const int i = n * 8 + g;
                const int j0 = kc * 16 + tid * 2;
                Bf[kc][n][0] = pack_bf2(__expf(trans[i * NTAGS + j0]),
                                        __expf(trans[i * NTAGS + j0 + 1]));
                Bf[kc][n][1] = pack_bf2(__expf(trans[i * NTAGS + j0 + 8]),
                                        __expf(trans[i * NTAGS + j0 + 9]));
            }
        // alpha one-hot at START (col 30 -> kc=1, +8 slot, tid==3, lo half)
        Aa[0][0] = 0u; Aa[0][1] = 0u;
        Aa[1][0] = 0u; Aa[1][1] = (tid == 3) ? 0x00003F80u : 0u;
#pragma unroll
        for (int u = 0; u < 4; u++)
#pragma unroll
            for (int n = 0; n < 4; n++) {
                rawA[u][n] = *(const float2*)(pb + (size_t)u * NTAGS + n * 8);
                rawB[u][n] = *(const float2*)(pb + (size_t)(4 + u) * NTAGS + n * 8);
            }
        for (int tb = 0; tb < HALF; tb += 8) {
            fwd_block(rawA, pb, tb,     Aa, Bf, esum, pend, v);
            fwd_block(rawB, pb, tb + 4, Aa, Bf, esum, pend, v);
        }
        // wait for beta, then combine
        __syncthreads();
        float s = 0.f;
#pragma unroll
        for (int n = 0; n < 4; n++) {
            s += v[n][0] * sbeta[g][n * 8 + tid * 2];
            s += v[n][1] * sbeta[g][n * 8 + tid * 2 + 1];
        }
        s += __shfl_xor_sync(0xffffffffu, s, 1);
        s += __shfl_xor_sync(0xffffffffu, s, 2);
        if (tid == 0)
            out[base + g] = (float)(
                (double)(esum + sesum[g]) * 0.6931471805599453 +
                log((double)s));
    } else {
        // ---- BACKWARD: B[k=i][n=j] = E[i,j] (transposed read of trans) ----
#pragma unroll
        for (int kc = 0; kc < 2; kc++)
#pragma unroll
            for (int n = 0; n < 4; n++) {
                const int j = n * 8 + g;
                const int i0 = kc * 16 + tid * 2;
                Bf[kc][n][0] = pack_bf2(__expf(trans[i0 * NTAGS + j]),
                                        __expf(trans[(i0 + 1) * NTAGS + j]));
                Bf[kc][n][1] = pack_bf2(__expf(trans[(i0 + 8) * NTAGS + j]),
                                        __expf(trans[(i0 + 9) * NTAGS + j]));
            }
        // beta_512 = eStop  (v layout: col = n*8 + tid*2 + k, all rows equal)
#pragma unroll
        for (int n = 0; n < 4; n++) {
            v[n][0] = __expf(trans[STOP_TAG * NTAGS + n * 8 + tid * 2]);
            v[n][1] = __expf(trans[STOP_TAG * NTAGS + n * 8 + tid * 2 + 1]);
        }
#pragma unroll
        for (int u = 0; u < 4; u++)
#pragma unroll
            for (int n = 0; n < 4; n++) {
                rawA[u][n] = *(const float2*)(
                    pb + (size_t)(SLEN - 1 - u) * NTAGS + n * 8);
                rawB[u][n] = *(const float2*)(
                    pb + (size_t)(SLEN - 5 - u) * NTAGS + n * 8);
            }
        for (int bb = 0; bb < HALF / 4; bb += 2) {
            bwd_block(rawA, pb, bb,     Aa, Bf, esum, pend, v);
            bwd_block(rawB, pb, bb + 1, Aa, Bf, esum, pend, v);
        }
        // publish beta + esum_b
#pragma unroll
        for (int n = 0; n < 4; n++) {
            sbeta[g][n * 8 + tid * 2]     = v[n][0];
            sbeta[g][n * 8 + tid * 2 + 1] = v[n][1];
        }
        if (tid == 0) sesum[g] = esum;
        __syncthreads();
    }
}

extern "C" void kernel_launch(void* const* d_in, const int* in_sizes, int n_in,
                              void* d_out, int out_size) {
    const float* feats = (const float*)d_in[0];
    const float* trans = (const float*)d_in[1];
    float* out = (float*)d_out;
    const int B = in_sizes[0] / (SLEN * NTAGS);
    crf_fwd_kernel<<<B / NB, 64>>>(feats, trans, out);  // fwd+bwd warp pair
}